// round 8
// baseline (speedup 1.0000x reference)
#include <cuda_runtime.h>
#include <math.h>

#define SENT 64
#define WRD  32
#define DIM  300
#define HID  50

// scratch (device globals; no allocation)
__device__ float g_pre[2 * SENT * 160];   // [dir][s][gate*50+o], row stride 160
__device__ float g_hsum2[64];             // backward-dir h sums
__device__ int   g_flag;                  // bwd-done flag (reset each call)

typedef unsigned long long u64;

__device__ __forceinline__ float tanhap(float x) {
    float y; asm("tanh.approx.f32 %0, %1;" : "=f"(y) : "f"(x)); return y;
}
__device__ __forceinline__ float tanh_acc(float x) {
    float e = __expf(-2.0f * fabsf(x));
    return copysignf(__fdividef(1.0f - e, 1.0f + e), x);
}
__device__ __forceinline__ float wred(float v) {
    #pragma unroll
    for (int o = 16; o; o >>= 1) v += __shfl_xor_sync(0xffffffffu, v, o);
    return v;
}
// packed f32x2 fma (SASS FFMA2) — 2 MACs per instruction
__device__ __forceinline__ u64 ffma2(u64 a, u64 b, u64 c) {
    u64 d; asm("fma.rn.f32x2 %0, %1, %2, %3;" : "=l"(d) : "l"(a), "l"(b), "l"(c));
    return d;
}
__device__ __forceinline__ u64 pack2(float lo, float hi) {
    u64 r; asm("mov.b64 %0, {%1, %2};" : "=l"(r) : "f"(lo), "f"(hi)); return r;
}
__device__ __forceinline__ float hadd2(u64 v) {
    float x, y; asm("mov.b64 {%0, %1}, %2;" : "=f"(x), "=f"(y) : "l"(v));
    return x + y;
}

// ---------------------------------------------------------------------------
// K1: per sentence -> window-mean trick -> rep[50] -> pre-activations
// ---------------------------------------------------------------------------
__global__ void __launch_bounds__(256, 1)
k1_rep_pre(const int* __restrict__ doc, const float* __restrict__ emb,
           const float* __restrict__ wl_w, const float* __restrict__ wl_b,
           const float* __restrict__ c1w, const float* __restrict__ c1b,
           const float* __restrict__ c2w, const float* __restrict__ c2b,
           const float* __restrict__ c3w, const float* __restrict__ c3b,
           const float* __restrict__ fiw, const float* __restrict__ fib,
           const float* __restrict__ ffw, const float* __restrict__ ffb,
           const float* __restrict__ fgw, const float* __restrict__ fgb,
           const float* __restrict__ biw, const float* __restrict__ bib,
           const float* __restrict__ bfw, const float* __restrict__ bfb,
           const float* __restrict__ bgw, const float* __restrict__ bgb)
{
    __shared__ __align__(16) float sV[6 * 304];
    __shared__ float sM[6][52];
    __shared__ float sRep[52];
    __shared__ int   sIdx[32];

    const int tid  = threadIdx.x;
    const int wid  = tid >> 5;
    const int lane = tid & 31;
    const int s    = blockIdx.x;

    if (tid < 32) sIdx[tid] = doc[s * WRD + tid];
    __syncthreads();

    // window means of embeddings (all 6 derive from full sum + 4 edge words)
    for (int d = tid; d < DIM; d += 256) {
        float z = 0.f, e0 = 0.f, e1 = 0.f, e30 = 0.f, e31 = 0.f;
        #pragma unroll
        for (int w = 0; w < 32; w++) {
            float v = __ldg(emb + (size_t)sIdx[w] * DIM + d);
            z += v;
            if (w == 0)  e0  = v;
            if (w == 1)  e1  = v;
            if (w == 30) e30 = v;
            if (w == 31) e31 = v;
        }
        sV[0 * 304 + d] = z * (1.f / 32.f);
        sV[1 * 304 + d] = (z - e31)       * (1.f / 31.f);
        sV[2 * 304 + d] = (z - e0)        * (1.f / 31.f);
        sV[3 * 304 + d] = (z - e30 - e31) * (1.f / 30.f);
        sV[4 * 304 + d] = (z - e0  - e31) * (1.f / 30.f);
        sV[5 * 304 + d] = (z - e0  - e1)  * (1.f / 30.f);
    }
    __syncthreads();

    // M[j][i] = wl_b[i] + <V[j], wl_w[i,:]> — warp-cooperative, coalesced float4
    for (int i = wid; i < HID; i += 8) {
        float a[6] = {0.f, 0.f, 0.f, 0.f, 0.f, 0.f};
        const float4* wr = (const float4*)(wl_w) + i * 75;
        for (int t = lane; t < 75; t += 32) {
            float4 w = __ldg(wr + t);
            #pragma unroll
            for (int j = 0; j < 6; j++) {
                float4 v = ((const float4*)(sV + j * 304))[t];
                a[j] = fmaf(w.x, v.x, fmaf(w.y, v.y, fmaf(w.z, v.z, fmaf(w.w, v.w, a[j]))));
            }
        }
        #pragma unroll
        for (int j = 0; j < 6; j++) a[j] = wred(a[j]);
        if (lane == 0) {
            float b = __ldg(wl_b + i);
            #pragma unroll
            for (int j = 0; j < 6; j++) sM[j][i] = a[j] + b;
        }
    }
    __syncthreads();

    // rep[o]: warp per output, lanes split the 50-dim sums (coalesced)
    for (int o = wid; o < HID; o += 8) {
        float a1 = 0.f, a2 = 0.f, a3 = 0.f;
        for (int i = lane; i < HID; i += 32) {
            a1 = fmaf(__ldg(c1w + o * 50 + i), sM[0][i], a1);
            float2 w2 = __ldg((const float2*)(c2w) + o * 50 + i);
            a2 = fmaf(w2.x, sM[1][i], fmaf(w2.y, sM[2][i], a2));
            const float* w3 = c3w + (o * 50 + i) * 3;
            a3 = fmaf(__ldg(w3 + 0), sM[3][i],
                 fmaf(__ldg(w3 + 1), sM[4][i],
                 fmaf(__ldg(w3 + 2), sM[5][i], a3)));
        }
        a1 = wred(a1); a2 = wred(a2); a3 = wred(a3);
        if (lane == 0) {
            a1 += __ldg(c1b + o); a2 += __ldg(c2b + o); a3 += __ldg(c3b + o);
            sRep[o] = (tanh_acc(a1) + tanh_acc(a2) + tanh_acc(a3)) * (1.f / 3.f);
        }
    }
    __syncthreads();

    // pre: 4 outputs per warp per iteration, interleaved warp reductions
    for (int g4 = wid; g4 < 75; g4 += 8) {
        const int qb = g4 * 4;
        const float* W[4]; const float* B[4]; int O[4];
        #pragma unroll
        for (int u = 0; u < 4; u++) {
            const int q = qb + u;
            const int dir = q / 150, r = q % 150;
            const int gate = r / 50;
            O[u] = r % 50;
            if (dir == 0) { W[u] = gate == 0 ? fiw : gate == 1 ? ffw : fgw;
                            B[u] = gate == 0 ? fib : gate == 1 ? ffb : fgb; }
            else          { W[u] = gate == 0 ? biw : gate == 1 ? bfw : bgw;
                            B[u] = gate == 0 ? bib : gate == 1 ? bfb : bgb; }
        }
        float a0 = 0.f, a1 = 0.f, a2 = 0.f, a3 = 0.f;
        for (int i = lane; i < HID; i += 32) {
            float r = sRep[i];
            a0 = fmaf(__ldg(W[0] + O[0] * 100 + i), r, a0);
            a1 = fmaf(__ldg(W[1] + O[1] * 100 + i), r, a1);
            a2 = fmaf(__ldg(W[2] + O[2] * 100 + i), r, a2);
            a3 = fmaf(__ldg(W[3] + O[3] * 100 + i), r, a3);
        }
        #pragma unroll
        for (int o = 16; o; o >>= 1) {
            a0 += __shfl_xor_sync(0xffffffffu, a0, o);
            a1 += __shfl_xor_sync(0xffffffffu, a1, o);
            a2 += __shfl_xor_sync(0xffffffffu, a2, o);
            a3 += __shfl_xor_sync(0xffffffffu, a3, o);
        }
        if (lane == 0) {
            float* dst = g_pre + (qb / 150) * SENT * 160 + s * 160 + (qb % 150);
            dst[0] = a0 + __ldg(B[0] + O[0]);
            dst[1] = a1 + __ldg(B[1] + O[1]);
            dst[2] = a2 + __ldg(B[2] + O[2]);
            dst[3] = a3 + __ldg(B[3] + O[3]);
        }
    }
}

// ---------------------------------------------------------------------------
// K2: serial gated scan, grid=2 (one block per direction), block=64 = 2 warps.
// Lane-owns-output: warp w, lane l (<25) owns h[w*25+l]; full 50-dim dots from
// register-resident f32x2 weights. NO shuffles; ONE nw=2 __syncthreads per
// step (ping-pong h). Sigmoid folded via 0.5-scaled i/f weights + pre-acts.
// ---------------------------------------------------------------------------
__global__ void __launch_bounds__(64, 1)
k2_scan(const float* __restrict__ fiw, const float* __restrict__ ffw,
        const float* __restrict__ fgw, const float* __restrict__ biw,
        const float* __restrict__ bfw, const float* __restrict__ bgw,
        const float* __restrict__ out_w, const float* __restrict__ out_b,
        float* __restrict__ out)
{
    __shared__ __align__(8) float sPre[SENT][152];
    __shared__ __align__(8) float sH[2][52];
    __shared__ float sOut[52];

    const int tid  = threadIdx.x;
    const int wid  = tid >> 5;
    const int lane = tid & 31;
    const int dir  = blockIdx.x;
    const bool act = (lane < 25);
    const int o    = wid * 25 + (act ? lane : 24);   // owned h index

    const float* Wi = dir ? biw : fiw;
    const float* Wf = dir ? bfw : ffw;
    const float* Wg = dir ? bgw : fgw;

    // register-resident recurrent weights, f32x2-packed;
    // i/f pre-scaled by 0.5 (sigmoid fold). 75 u64 regs per lane.
    u64 wi2[25], wf2[25], wg2[25];
    {
        const float2* bi = (const float2*)(Wi + o * 100 + 50);
        const float2* bf = (const float2*)(Wf + o * 100 + 50);
        const float2* bg = (const float2*)(Wg + o * 100 + 50);
        #pragma unroll
        for (int k = 0; k < 25; k++) {
            float2 vi = __ldg(bi + k);
            float2 vf = __ldg(bf + k);
            float2 vg = __ldg(bg + k);
            wi2[k] = pack2(0.5f * vi.x, 0.5f * vi.y);
            wf2[k] = pack2(0.5f * vf.x, 0.5f * vf.y);
            wg2[k] = pack2(vg.x, vg.y);
        }
    }

    // load pre-activations (float2); scale i/f rows (q<100) by 0.5
    for (int k = tid; k < SENT * 75; k += 64) {
        int ss = k / 75, q2 = (k % 75) * 2;
        float2 v = *(const float2*)&g_pre[(dir * SENT + ss) * 160 + q2];
        if (q2 < 100) { v.x *= 0.5f; v.y *= 0.5f; }
        *(float2*)&sPre[ss][q2] = v;
    }
    if (tid < 52) { sH[0][tid] = 0.f; sH[1][tid] = 0.f; }
    float hsum = 0.f;
    __syncthreads();

    const float* pp = dir ? &sPre[SENT - 1][0] : &sPre[0][0];
    const int dstride = dir ? -152 : 152;

    #pragma unroll 1
    for (int step = 0; step < SENT; step += 2) {
        #pragma unroll
        for (int half = 0; half < 2; half++) {
            const int rb = half, wb = half ^ 1;
            u64 a0 = 0ull, a1 = 0ull, a2 = 0ull;
            #pragma unroll
            for (int k = 0; k < 25; k++) {
                u64 hv = *(const u64*)&sH[rb][2 * k];   // broadcast, conflict-free
                a0 = ffma2(wi2[k], hv, a0);
                a1 = ffma2(wf2[k], hv, a1);
                a2 = ffma2(wg2[k], hv, a2);
            }
            float s0 = hadd2(a0), s1 = hadd2(a1), s2 = hadd2(a2);
            float hp = sH[rb][o];
            float ti = tanhap(s0 + pp[o]);          // = tanh(i_pre/2)
            float tf = tanhap(s1 + pp[50 + o]);     // = tanh(f_pre/2)
            float gv = tanhap(s2 + pp[100 + o]);
            // i*g + f*h = 0.5*((ti*gv+gv) + (tf*hp+hp))
            float hn = tanhap(0.5f * (fmaf(ti, gv, gv) + fmaf(tf, hp, hp)));
            if (act) { sH[wb][o] = hn; hsum += hn; }
            pp += dstride;
            __syncthreads();   // nw=2 barrier (floor ~7 cyc)
        }
    }

    if (dir == 1) {
        if (act) g_hsum2[o] = hsum;
        __syncthreads();
        __threadfence();
        if (tid == 0) atomicExch(&g_flag, 1);
        return;
    }

    // ----- block 0: wait for bwd, produce softmax output -----
    if (act) sOut[o] = hsum;
    if (tid == 0) { while (atomicAdd(&g_flag, 0) < 1) { } }
    __threadfence();
    __syncthreads();

    if (tid < 32) {
        float lg[5];
        #pragma unroll
        for (int c = 0; c < 5; c++) {
            float acc = 0.f;
            for (int j = lane; j < 100; j += 32) {
                float g = (j < 50) ? sOut[j] : __ldcg(&g_hsum2[j - 50]);
                acc = fmaf(__ldg(out_w + c * 100 + j), g, acc);
            }
            acc = wred(acc);
            lg[c] = acc * (1.f / 64.f) + __ldg(out_b + c);
        }
        float m = lg[0];
        #pragma unroll
        for (int c = 1; c < 5; c++) m = fmaxf(m, lg[c]);
        float e[5], sum = 0.f;
        #pragma unroll
        for (int c = 0; c < 5; c++) { e[c] = __expf(lg[c] - m); sum += e[c]; }
        float inv = __fdividef(1.f, sum);
        if (lane < 5) out[lane] = e[lane] * inv;
    }
    if (tid == 0) atomicExch(&g_flag, 0);   // reset for next graph replay
}

// ---------------------------------------------------------------------------
extern "C" void kernel_launch(void* const* d_in, const int* in_sizes, int n_in,
                              void* d_out, int out_size)
{
    const int*   doc  = (const int*)  d_in[0];
    const float* emb  = (const float*)d_in[1];
    const float* wl_w = (const float*)d_in[2];
    const float* wl_b = (const float*)d_in[3];
    const float* c1w  = (const float*)d_in[4];
    const float* c1b  = (const float*)d_in[5];
    const float* c2w  = (const float*)d_in[6];
    const float* c2b  = (const float*)d_in[7];
    const float* c3w  = (const float*)d_in[8];
    const float* c3b  = (const float*)d_in[9];
    const float* fiw  = (const float*)d_in[10];
    const float* fib  = (const float*)d_in[11];
    const float* ffw  = (const float*)d_in[12];
    const float* ffb  = (const float*)d_in[13];
    const float* fgw  = (const float*)d_in[14];
    const float* fgb  = (const float*)d_in[15];
    const float* biw  = (const float*)d_in[16];
    const float* bib  = (const float*)d_in[17];
    const float* bfw  = (const float*)d_in[18];
    const float* bfb  = (const float*)d_in[19];
    const float* bgw  = (const float*)d_in[20];
    const float* bgb  = (const float*)d_in[21];
    const float* outw = (const float*)d_in[22];
    const float* outb = (const float*)d_in[23];

    k1_rep_pre<<<SENT, 256>>>(doc, emb, wl_w, wl_b, c1w, c1b, c2w, c2b, c3w, c3b,
                              fiw, fib, ffw, ffb, fgw, fgb,
                              biw, bib, bfw, bfb, bgw, bgb);
    k2_scan<<<2, 64>>>(fiw, ffw, fgw, biw, bfw, bgw, outw, outb, (float*)d_out);
}

// round 9
// speedup vs baseline: 1.2414x; 1.2414x over previous
#include <cuda_runtime.h>
#include <math.h>

#define SENT 64
#define WRD  32
#define DIM  300
#define HID  50

// scratch (device globals; no allocation)
// transposed pre-activations: row = dir*150 + gate*50 + h  (gate 0=i,1=f,2=g),
// column = step (dir 1 stored time-reversed). i/f rows pre-scaled by 0.5.
__device__ float g_pre_t[300 * 64];
__device__ float g_hsum2[64];             // backward-dir h sums
__device__ int   g_flag;                  // bwd-done flag (reset each call)

typedef unsigned long long u64;

__device__ __forceinline__ float tanhap(float x) {
    float y; asm("tanh.approx.f32 %0, %1;" : "=f"(y) : "f"(x)); return y;
}
__device__ __forceinline__ float tanh_acc(float x) {
    float e = __expf(-2.0f * fabsf(x));
    return copysignf(__fdividef(1.0f - e, 1.0f + e), x);
}
__device__ __forceinline__ float wred(float v) {
    #pragma unroll
    for (int o = 16; o; o >>= 1) v += __shfl_xor_sync(0xffffffffu, v, o);
    return v;
}
// packed f32x2 fma (SASS FFMA2) — 2 MACs per instruction
__device__ __forceinline__ u64 ffma2(u64 a, u64 b, u64 c) {
    u64 d; asm("fma.rn.f32x2 %0, %1, %2, %3;" : "=l"(d) : "l"(a), "l"(b), "l"(c));
    return d;
}
__device__ __forceinline__ u64 pack2(float lo, float hi) {
    u64 r; asm("mov.b64 %0, {%1, %2};" : "=l"(r) : "f"(lo), "f"(hi)); return r;
}
__device__ __forceinline__ float hadd2(u64 v) {
    float x, y; asm("mov.b64 {%0, %1}, %2;" : "=f"(x), "=f"(y) : "l"(v));
    return x + y;
}

// ---------------------------------------------------------------------------
// K1: per sentence -> window-mean trick -> rep[50] -> transposed pre-acts
// ---------------------------------------------------------------------------
__global__ void __launch_bounds__(512, 1)
k1_rep_pre(const int* __restrict__ doc, const float* __restrict__ emb,
           const float* __restrict__ wl_w, const float* __restrict__ wl_b,
           const float* __restrict__ c1w, const float* __restrict__ c1b,
           const float* __restrict__ c2w, const float* __restrict__ c2b,
           const float* __restrict__ c3w, const float* __restrict__ c3b,
           const float* __restrict__ fiw, const float* __restrict__ fib,
           const float* __restrict__ ffw, const float* __restrict__ ffb,
           const float* __restrict__ fgw, const float* __restrict__ fgb,
           const float* __restrict__ biw, const float* __restrict__ bib,
           const float* __restrict__ bfw, const float* __restrict__ bfb,
           const float* __restrict__ bgw, const float* __restrict__ bgb)
{
    __shared__ __align__(16) float sV[6 * 304];
    __shared__ float sM[6][52];
    __shared__ float sRep[52];
    __shared__ int   sIdx[32];

    const int tid  = threadIdx.x;
    const int wid  = tid >> 5;
    const int lane = tid & 31;
    const int s    = blockIdx.x;

    if (tid < 32) sIdx[tid] = doc[s * WRD + tid];
    __syncthreads();

    // window means of embeddings (all 6 derive from full sum + 4 edge words)
    for (int d = tid; d < DIM; d += 512) {
        float z = 0.f, e0 = 0.f, e1 = 0.f, e30 = 0.f, e31 = 0.f;
        #pragma unroll
        for (int w = 0; w < 32; w++) {
            float v = __ldg(emb + (size_t)sIdx[w] * DIM + d);
            z += v;
            if (w == 0)  e0  = v;
            if (w == 1)  e1  = v;
            if (w == 30) e30 = v;
            if (w == 31) e31 = v;
        }
        sV[0 * 304 + d] = z * (1.f / 32.f);
        sV[1 * 304 + d] = (z - e31)       * (1.f / 31.f);
        sV[2 * 304 + d] = (z - e0)        * (1.f / 31.f);
        sV[3 * 304 + d] = (z - e30 - e31) * (1.f / 30.f);
        sV[4 * 304 + d] = (z - e0  - e31) * (1.f / 30.f);
        sV[5 * 304 + d] = (z - e0  - e1)  * (1.f / 30.f);
    }
    __syncthreads();

    // M[j][i] = wl_b[i] + <V[j], wl_w[i,:]> — warp-cooperative, coalesced float4
    for (int i = wid; i < HID; i += 16) {
        float a[6] = {0.f, 0.f, 0.f, 0.f, 0.f, 0.f};
        const float4* wr = (const float4*)(wl_w) + i * 75;
        for (int t = lane; t < 75; t += 32) {
            float4 w = __ldg(wr + t);
            #pragma unroll
            for (int j = 0; j < 6; j++) {
                float4 v = ((const float4*)(sV + j * 304))[t];
                a[j] = fmaf(w.x, v.x, fmaf(w.y, v.y, fmaf(w.z, v.z, fmaf(w.w, v.w, a[j]))));
            }
        }
        #pragma unroll
        for (int j = 0; j < 6; j++) a[j] = wred(a[j]);
        if (lane == 0) {
            float b = __ldg(wl_b + i);
            #pragma unroll
            for (int j = 0; j < 6; j++) sM[j][i] = a[j] + b;
        }
    }
    __syncthreads();

    // rep[o]: warp per output, lanes split the 50-dim sums (coalesced)
    for (int o = wid; o < HID; o += 16) {
        float a1 = 0.f, a2 = 0.f, a3 = 0.f;
        for (int i = lane; i < HID; i += 32) {
            a1 = fmaf(__ldg(c1w + o * 50 + i), sM[0][i], a1);
            float2 w2 = __ldg((const float2*)(c2w) + o * 50 + i);
            a2 = fmaf(w2.x, sM[1][i], fmaf(w2.y, sM[2][i], a2));
            const float* w3 = c3w + (o * 50 + i) * 3;
            a3 = fmaf(__ldg(w3 + 0), sM[3][i],
                 fmaf(__ldg(w3 + 1), sM[4][i],
                 fmaf(__ldg(w3 + 2), sM[5][i], a3)));
        }
        a1 = wred(a1); a2 = wred(a2); a3 = wred(a3);
        if (lane == 0) {
            a1 += __ldg(c1b + o); a2 += __ldg(c2b + o); a3 += __ldg(c3b + o);
            sRep[o] = (tanh_acc(a1) + tanh_acc(a2) + tanh_acc(a3)) * (1.f / 3.f);
        }
    }
    __syncthreads();

    // pre: 4 outputs per warp per iteration, interleaved warp reductions.
    // Store TRANSPOSED: g_pre_t[q*64 + col], dir1 time-reversed, i/f rows *0.5.
    for (int g4 = wid; g4 < 75; g4 += 16) {
        const int qb = g4 * 4;
        const float* W[4]; const float* B[4]; int O[4];
        #pragma unroll
        for (int u = 0; u < 4; u++) {
            const int q = qb + u;
            const int dir = q / 150, r = q % 150;
            const int gate = r / 50;
            O[u] = r % 50;
            if (dir == 0) { W[u] = gate == 0 ? fiw : gate == 1 ? ffw : fgw;
                            B[u] = gate == 0 ? fib : gate == 1 ? ffb : fgb; }
            else          { W[u] = gate == 0 ? biw : gate == 1 ? bfw : bgw;
                            B[u] = gate == 0 ? bib : gate == 1 ? bfb : bgb; }
        }
        float a0 = 0.f, a1 = 0.f, a2 = 0.f, a3 = 0.f;
        for (int i = lane; i < HID; i += 32) {
            float r = sRep[i];
            a0 = fmaf(__ldg(W[0] + O[0] * 100 + i), r, a0);
            a1 = fmaf(__ldg(W[1] + O[1] * 100 + i), r, a1);
            a2 = fmaf(__ldg(W[2] + O[2] * 100 + i), r, a2);
            a3 = fmaf(__ldg(W[3] + O[3] * 100 + i), r, a3);
        }
        #pragma unroll
        for (int o = 16; o; o >>= 1) {
            a0 += __shfl_xor_sync(0xffffffffu, a0, o);
            a1 += __shfl_xor_sync(0xffffffffu, a1, o);
            a2 += __shfl_xor_sync(0xffffffffu, a2, o);
            a3 += __shfl_xor_sync(0xffffffffu, a3, o);
        }
        if (lane == 0) {
            float v[4] = {a0, a1, a2, a3};
            #pragma unroll
            for (int u = 0; u < 4; u++) {
                const int q = qb + u;
                const int dir = q / 150, r = q % 150;
                const int col = dir ? (SENT - 1 - s) : s;
                float val = v[u] + __ldg(B[u] + O[u]);
                if (r < 100) val *= 0.5f;             // sigmoid fold for i/f
                g_pre_t[q * 64 + col] = val;
            }
        }
    }
}

// ---------------------------------------------------------------------------
// K2: serial gated scan, grid=2 (block per direction), block=256, split-4.
// No sPre smem (per-thread float4 streaming of transposed pre), no branches
// in the step loop (redundant same-address STS, padded sH + zero-pad weights),
// hp register-carried, sigmoid folded. One __syncthreads per step.
// ---------------------------------------------------------------------------
__global__ void __launch_bounds__(256, 1)
k2_scan(const float* __restrict__ fiw, const float* __restrict__ ffw,
        const float* __restrict__ fgw, const float* __restrict__ biw,
        const float* __restrict__ bfw, const float* __restrict__ bgw,
        const float* __restrict__ out_w, const float* __restrict__ out_b,
        float* __restrict__ out)
{
    __shared__ __align__(8) float sH[2][64];
    __shared__ float sOut[52];

    const int tid  = threadIdx.x;
    const int lane = tid & 31;
    const int dir  = blockIdx.x;
    const int p    = tid & 3;
    const int h    = tid >> 2;          // 0..63
    const bool act = (h < HID);
    const int hc   = act ? h : HID - 1;
    const int j0   = p * 14;            // 4 x 14 covers 50 (zero-padded)

    const float* Wi = dir ? biw : fiw;
    const float* Wf = dir ? bfw : ffw;
    const float* Wg = dir ? bgw : fgw;

    // recurrent weights f32x2-packed; i/f pre-scaled 0.5 (sigmoid fold);
    // MUST be zero beyond j>=50 (padded sH slots hold garbage).
    u64 wi2[7], wf2[7], wg2[7];
    #pragma unroll
    for (int k = 0; k < 7; k++) {
        const int ja = j0 + 2 * k, jb = ja + 1;
        const float* bi = Wi + hc * 100 + 50;
        const float* bf = Wf + hc * 100 + 50;
        const float* bg = Wg + hc * 100 + 50;
        float ilo = (ja < HID) ? 0.5f * __ldg(bi + ja) : 0.f;
        float ihi = (jb < HID) ? 0.5f * __ldg(bi + jb) : 0.f;
        float flo = (ja < HID) ? 0.5f * __ldg(bf + ja) : 0.f;
        float fhi = (jb < HID) ? 0.5f * __ldg(bf + jb) : 0.f;
        float glo = (ja < HID) ? __ldg(bg + ja) : 0.f;
        float ghi = (jb < HID) ? __ldg(bg + jb) : 0.f;
        wi2[k] = pack2(ilo, ihi);
        wf2[k] = pack2(flo, fhi);
        wg2[k] = pack2(glo, ghi);
    }

    // per-thread streaming pointers into transposed pre (16 float4 per row)
    const float4* Pi = (const float4*)(g_pre_t + (dir * 150 + hc) * 64);
    const float4* Pf = (const float4*)(g_pre_t + (dir * 150 + 50 + hc) * 64);
    const float4* Pg = (const float4*)(g_pre_t + (dir * 150 + 100 + hc) * 64);
    float4 bi4 = __ldcg(Pi), bf4 = __ldcg(Pf), bg4 = __ldcg(Pg);

    if (tid < 64) { sH[0][tid] = 0.f; sH[1][tid] = 0.f; }
    float hsum = 0.f, hp = 0.f;
    __syncthreads();

    #pragma unroll 1
    for (int c = 0; c < 16; c++) {
        float4 ni = bi4, nf = bf4, ng = bg4;
        if (c < 15) { ni = __ldcg(Pi + c + 1); nf = __ldcg(Pf + c + 1); ng = __ldcg(Pg + c + 1); }
        #pragma unroll
        for (int k = 0; k < 4; k++) {
            const int rb = k & 1, wb = rb ^ 1;
            u64 a0 = 0ull, a1 = 0ull, a2 = 0ull;
            #pragma unroll
            for (int t = 0; t < 7; t++) {
                u64 hv = *(const u64*)&sH[rb][j0 + 2 * t];   // 4 distinct addrs/warp, broadcast
                a0 = ffma2(wi2[t], hv, a0);
                a1 = ffma2(wf2[t], hv, a1);
                a2 = ffma2(wg2[t], hv, a2);
            }
            float s0 = hadd2(a0), s1 = hadd2(a1), s2 = hadd2(a2);
            s0 += __shfl_xor_sync(0xffffffffu, s0, 1);
            s1 += __shfl_xor_sync(0xffffffffu, s1, 1);
            s2 += __shfl_xor_sync(0xffffffffu, s2, 1);
            s0 += __shfl_xor_sync(0xffffffffu, s0, 2);
            s1 += __shfl_xor_sync(0xffffffffu, s1, 2);
            s2 += __shfl_xor_sync(0xffffffffu, s2, 2);
            const float pik = (k == 0) ? bi4.x : (k == 1) ? bi4.y : (k == 2) ? bi4.z : bi4.w;
            const float pfk = (k == 0) ? bf4.x : (k == 1) ? bf4.y : (k == 2) ? bf4.z : bf4.w;
            const float pgk = (k == 0) ? bg4.x : (k == 1) ? bg4.y : (k == 2) ? bg4.z : bg4.w;
            float ti = tanhap(s0 + pik);         // tanh(i_pre/2)
            float tf = tanhap(s1 + pfk);         // tanh(f_pre/2)
            float gv = tanhap(s2 + pgk);
            // i*g + f*h = 0.5*((ti*gv+gv) + (tf*hp+hp))
            float hn = tanhap(0.5f * (fmaf(ti, gv, gv) + fmaf(tf, hp, hp)));
            sH[wb][h] = hn;       // all 4 lanes write same value (no branch)
            hp = hn;
            hsum += hn;
            __syncthreads();
        }
        bi4 = ni; bf4 = nf; bg4 = ng;
    }

    if (dir == 1) {
        if (p == 0 && act) g_hsum2[h] = hsum;
        __syncthreads();
        __threadfence();
        if (tid == 0) atomicExch(&g_flag, 1);
        return;
    }

    // ----- block 0: wait for bwd, produce softmax output -----
    if (p == 0 && act) sOut[h] = hsum;
    if (tid == 0) { while (atomicAdd(&g_flag, 0) < 1) { } }
    __threadfence();
    __syncthreads();

    if (tid < 32) {
        float lg[5];
        #pragma unroll
        for (int c = 0; c < 5; c++) {
            float acc = 0.f;
            for (int j = lane; j < 100; j += 32) {
                float g = (j < 50) ? sOut[j] : __ldcg(&g_hsum2[j - 50]);
                acc = fmaf(__ldg(out_w + c * 100 + j), g, acc);
            }
            acc = wred(acc);
            lg[c] = acc * (1.f / 64.f) + __ldg(out_b + c);
        }
        float m = lg[0];
        #pragma unroll
        for (int c = 1; c < 5; c++) m = fmaxf(m, lg[c]);
        float e[5], sum = 0.f;
        #pragma unroll
        for (int c = 0; c < 5; c++) { e[c] = __expf(lg[c] - m); sum += e[c]; }
        float inv = __fdividef(1.f, sum);
        if (lane < 5) out[lane] = e[lane] * inv;
    }
    if (tid == 0) atomicExch(&g_flag, 0);   // reset for next graph replay
}

// ---------------------------------------------------------------------------
extern "C" void kernel_launch(void* const* d_in, const int* in_sizes, int n_in,
                              void* d_out, int out_size)
{
    const int*   doc  = (const int*)  d_in[0];
    const float* emb  = (const float*)d_in[1];
    const float* wl_w = (const float*)d_in[2];
    const float* wl_b = (const float*)d_in[3];
    const float* c1w  = (const float*)d_in[4];
    const float* c1b  = (const float*)d_in[5];
    const float* c2w  = (const float*)d_in[6];
    const float* c2b  = (const float*)d_in[7];
    const float* c3w  = (const float*)d_in[8];
    const float* c3b  = (const float*)d_in[9];
    const float* fiw  = (const float*)d_in[10];
    const float* fib  = (const float*)d_in[11];
    const float* ffw  = (const float*)d_in[12];
    const float* ffb  = (const float*)d_in[13];
    const float* fgw  = (const float*)d_in[14];
    const float* fgb  = (const float*)d_in[15];
    const float* biw  = (const float*)d_in[16];
    const float* bib  = (const float*)d_in[17];
    const float* bfw  = (const float*)d_in[18];
    const float* bfb  = (const float*)d_in[19];
    const float* bgw  = (const float*)d_in[20];
    const float* bgb  = (const float*)d_in[21];
    const float* outw = (const float*)d_in[22];
    const float* outb = (const float*)d_in[23];

    k1_rep_pre<<<SENT, 512>>>(doc, emb, wl_w, wl_b, c1w, c1b, c2w, c2b, c3w, c3b,
                              fiw, fib, ffw, ffb, fgw, fgb,
                              biw, bib, bfw, bfb, bgw, bgb);
    k2_scan<<<2, 256>>>(fiw, ffw, fgw, biw, bfw, bgw, outw, outb, (float*)d_out);
}